// round 2
// baseline (speedup 1.0000x reference)
#include <cuda_runtime.h>

// Problem constants
#define B_    2
#define S_    2048
#define D_    1024
#define H_    16
#define DK_   64
#define BH_   (B_*H_)        // 32
#define MROWS (B_*S_)        // 4096
#define OUT_OFF ((size_t)B_*S_*D_)   // 4194304 floats: start of attention_weights

// Scratch (device globals — no allocation allowed)
__device__ float g_q[BH_*S_*DK_];    // [B,H,S,DK]
__device__ float g_k[BH_*S_*DK_];
__device__ float g_v[BH_*S_*DK_];
__device__ float g_ctx[MROWS*D_];    // [B,S,D] merged-head context

// ---------------------------------------------------------------------------
// Tiled fp32 GEMM building blocks: BM=BN=64, BK=16, 256 threads, 4x4 per thread
// A is staged transposed in smem (Ast[k][m], padded stride 68) so the inner
// loop does 2x LDS.128 per 16 FMA.
// ---------------------------------------------------------------------------

// QKV projection: out = X[4096,1024] @ W[1024,1024] + bias, written split-head
// dst_sel: 0 -> g_q, 1 -> g_k, 2 -> g_v   layout [B,H,S,DK]
__global__ void proj_kernel(const float* __restrict__ X,
                            const float* __restrict__ W,
                            const float* __restrict__ bias,
                            int dst_sel)
{
    __shared__ float Ast[16][68];
    __shared__ float Bs[16][64];
    const int m0 = blockIdx.y * 64;
    const int n0 = blockIdx.x * 64;
    const int tid = threadIdx.x;
    const int tx = tid & 15, ty = tid >> 4;
    float acc[4][4] = {};

    for (int k0 = 0; k0 < D_; k0 += 16) {
        {
            int ar = tid >> 2, ac = (tid & 3) * 4;
            float4 v = *(const float4*)&X[(size_t)(m0 + ar) * D_ + k0 + ac];
            Ast[ac+0][ar] = v.x; Ast[ac+1][ar] = v.y;
            Ast[ac+2][ar] = v.z; Ast[ac+3][ar] = v.w;
        }
        {
            int br = tid >> 4, bc = (tid & 15) * 4;
            *(float4*)&Bs[br][bc] = *(const float4*)&W[(size_t)(k0 + br) * D_ + n0 + bc];
        }
        __syncthreads();
        #pragma unroll
        for (int kk = 0; kk < 16; kk++) {
            float4 a4 = *(const float4*)&Ast[kk][ty*4];
            float4 b4 = *(const float4*)&Bs[kk][tx*4];
            float av[4] = {a4.x, a4.y, a4.z, a4.w};
            float bv[4] = {b4.x, b4.y, b4.z, b4.w};
            #pragma unroll
            for (int i = 0; i < 4; i++)
                #pragma unroll
                for (int j = 0; j < 4; j++)
                    acc[i][j] += av[i] * bv[j];
        }
        __syncthreads();
    }

    float* dst = (dst_sel == 0) ? g_q : (dst_sel == 1) ? g_k : g_v;
    #pragma unroll
    for (int i = 0; i < 4; i++) {
        int m = m0 + ty*4 + i;
        int b = m >> 11, s = m & (S_ - 1);
        #pragma unroll
        for (int j = 0; j < 4; j++) {
            int n = n0 + tx*4 + j;
            int h = n >> 6, d = n & (DK_ - 1);
            dst[(((size_t)(b*H_ + h))*S_ + s)*DK_ + d] = acc[i][j] + bias[n];
        }
    }
}

// Scores: C[bh] = (Q[bh] @ K[bh]^T) * 0.125  -> attn region of d_out (raw softmax input)
// NT GEMM: M=N=2048, K=64
__global__ void scores_kernel(float* __restrict__ attn)
{
    __shared__ float Ast[16][68];
    __shared__ float Bst[16][68];
    const int bh = blockIdx.z;
    const float* Q = g_q + (size_t)bh * S_ * DK_;
    const float* Km = g_k + (size_t)bh * S_ * DK_;
    float* C = attn + (size_t)bh * S_ * S_;
    const int m0 = blockIdx.y * 64;
    const int n0 = blockIdx.x * 64;
    const int tid = threadIdx.x;
    const int tx = tid & 15, ty = tid >> 4;
    float acc[4][4] = {};

    #pragma unroll
    for (int k0 = 0; k0 < DK_; k0 += 16) {
        {
            int ar = tid >> 2, ac = (tid & 3) * 4;
            float4 v = *(const float4*)&Q[(size_t)(m0 + ar) * DK_ + k0 + ac];
            Ast[ac+0][ar] = v.x; Ast[ac+1][ar] = v.y;
            Ast[ac+2][ar] = v.z; Ast[ac+3][ar] = v.w;
        }
        {
            int nr = tid >> 2, nc = (tid & 3) * 4;
            float4 v = *(const float4*)&Km[(size_t)(n0 + nr) * DK_ + k0 + nc];
            Bst[nc+0][nr] = v.x; Bst[nc+1][nr] = v.y;
            Bst[nc+2][nr] = v.z; Bst[nc+3][nr] = v.w;
        }
        __syncthreads();
        #pragma unroll
        for (int kk = 0; kk < 16; kk++) {
            float4 a4 = *(const float4*)&Ast[kk][ty*4];
            float4 b4 = *(const float4*)&Bst[kk][tx*4];
            float av[4] = {a4.x, a4.y, a4.z, a4.w};
            float bv[4] = {b4.x, b4.y, b4.z, b4.w};
            #pragma unroll
            for (int i = 0; i < 4; i++)
                #pragma unroll
                for (int j = 0; j < 4; j++)
                    acc[i][j] += av[i] * bv[j];
        }
        __syncthreads();
    }

    #pragma unroll
    for (int i = 0; i < 4; i++) {
        int m = m0 + ty*4 + i;
        #pragma unroll
        for (int j = 0; j < 4; j++) {
            int n = n0 + tx*4 + j;
            C[(size_t)m * S_ + n] = acc[i][j] * 0.125f;
        }
    }
}

// Row softmax in place over attn rows of length S_=2048. One block per row.
__global__ void softmax_kernel(float* __restrict__ attn)
{
    const size_t row = blockIdx.x;
    float* p = attn + row * (size_t)S_;
    const int tid = threadIdx.x;
    const int lane = tid & 31, wid = tid >> 5;
    __shared__ float red[8];

    float4 v0 = ((const float4*)p)[tid];
    float4 v1 = ((const float4*)p)[tid + 256];

    float m = fmaxf(fmaxf(fmaxf(v0.x, v0.y), fmaxf(v0.z, v0.w)),
                    fmaxf(fmaxf(v1.x, v1.y), fmaxf(v1.z, v1.w)));
    #pragma unroll
    for (int o = 16; o; o >>= 1) m = fmaxf(m, __shfl_xor_sync(0xffffffffu, m, o));
    if (lane == 0) red[wid] = m;
    __syncthreads();
    if (tid == 0) {
        float mm = red[0];
        #pragma unroll
        for (int i = 1; i < 8; i++) mm = fmaxf(mm, red[i]);
        red[0] = mm;
    }
    __syncthreads();
    m = red[0];
    __syncthreads();

    float4 e0, e1;
    e0.x = __expf(v0.x - m); e0.y = __expf(v0.y - m);
    e0.z = __expf(v0.z - m); e0.w = __expf(v0.w - m);
    e1.x = __expf(v1.x - m); e1.y = __expf(v1.y - m);
    e1.z = __expf(v1.z - m); e1.w = __expf(v1.w - m);

    float s = (e0.x + e0.y + e0.z + e0.w) + (e1.x + e1.y + e1.z + e1.w);
    #pragma unroll
    for (int o = 16; o; o >>= 1) s += __shfl_xor_sync(0xffffffffu, s, o);
    if (lane == 0) red[wid] = s;
    __syncthreads();
    if (tid == 0) {
        float ss = 0.f;
        #pragma unroll
        for (int i = 0; i < 8; i++) ss += red[i];
        red[0] = ss;
    }
    __syncthreads();
    float inv = 1.0f / red[0];

    e0.x *= inv; e0.y *= inv; e0.z *= inv; e0.w *= inv;
    e1.x *= inv; e1.y *= inv; e1.z *= inv; e1.w *= inv;
    ((float4*)p)[tid] = e0;
    ((float4*)p)[tid + 256] = e1;
}

// Context: ctx[b,s,h*64+d] = sum_k attn[bh,s,k] * V[bh,k,d]
// NN GEMM per bh: M=2048, N=64, K=2048
__global__ void av_kernel(const float* __restrict__ attn)
{
    __shared__ float Ast[16][68];
    __shared__ float Bs[16][64];
    const int bh = blockIdx.z;
    const int b = bh >> 4, h = bh & 15;
    const float* A = attn + (size_t)bh * S_ * S_;
    const float* V = g_v + (size_t)bh * S_ * DK_;
    const int m0 = blockIdx.y * 64;
    const int tid = threadIdx.x;
    const int tx = tid & 15, ty = tid >> 4;
    float acc[4][4] = {};

    for (int k0 = 0; k0 < S_; k0 += 16) {
        {
            int ar = tid >> 2, ac = (tid & 3) * 4;
            float4 v = *(const float4*)&A[(size_t)(m0 + ar) * S_ + k0 + ac];
            Ast[ac+0][ar] = v.x; Ast[ac+1][ar] = v.y;
            Ast[ac+2][ar] = v.z; Ast[ac+3][ar] = v.w;
        }
        {
            int br = tid >> 4, bc = (tid & 15) * 4;
            *(float4*)&Bs[br][bc] = *(const float4*)&V[(size_t)(k0 + br) * DK_ + bc];
        }
        __syncthreads();
        #pragma unroll
        for (int kk = 0; kk < 16; kk++) {
            float4 a4 = *(const float4*)&Ast[kk][ty*4];
            float4 b4 = *(const float4*)&Bs[kk][tx*4];
            float av[4] = {a4.x, a4.y, a4.z, a4.w};
            float bv[4] = {b4.x, b4.y, b4.z, b4.w};
            #pragma unroll
            for (int i = 0; i < 4; i++)
                #pragma unroll
                for (int j = 0; j < 4; j++)
                    acc[i][j] += av[i] * bv[j];
        }
        __syncthreads();
    }

    #pragma unroll
    for (int i = 0; i < 4; i++) {
        int s = m0 + ty*4 + i;
        #pragma unroll
        for (int j = 0; j < 4; j++) {
            int d = tx*4 + j;
            g_ctx[((size_t)(b*S_ + s))*D_ + h*DK_ + d] = acc[i][j];
        }
    }
}

// Output projection: out = ctx[4096,1024] @ Wo + bo -> d_out (plain row-major)
__global__ void out_kernel(const float* __restrict__ W,
                           const float* __restrict__ bias,
                           float* __restrict__ out)
{
    __shared__ float Ast[16][68];
    __shared__ float Bs[16][64];
    const int m0 = blockIdx.y * 64;
    const int n0 = blockIdx.x * 64;
    const int tid = threadIdx.x;
    const int tx = tid & 15, ty = tid >> 4;
    float acc[4][4] = {};

    for (int k0 = 0; k0 < D_; k0 += 16) {
        {
            int ar = tid >> 2, ac = (tid & 3) * 4;
            float4 v = *(const float4*)&g_ctx[(size_t)(m0 + ar) * D_ + k0 + ac];
            Ast[ac+0][ar] = v.x; Ast[ac+1][ar] = v.y;
            Ast[ac+2][ar] = v.z; Ast[ac+3][ar] = v.w;
        }
        {
            int br = tid >> 4, bc = (tid & 15) * 4;
            *(float4*)&Bs[br][bc] = *(const float4*)&W[(size_t)(k0 + br) * D_ + n0 + bc];
        }
        __syncthreads();
        #pragma unroll
        for (int kk = 0; kk < 16; kk++) {
            float4 a4 = *(const float4*)&Ast[kk][ty*4];
            float4 b4 = *(const float4*)&Bs[kk][tx*4];
            float av[4] = {a4.x, a4.y, a4.z, a4.w};
            float bv[4] = {b4.x, b4.y, b4.z, b4.w};
            #pragma unroll
            for (int i = 0; i < 4; i++)
                #pragma unroll
                for (int j = 0; j < 4; j++)
                    acc[i][j] += av[i] * bv[j];
        }
        __syncthreads();
    }

    #pragma unroll
    for (int i = 0; i < 4; i++) {
        int m = m0 + ty*4 + i;
        #pragma unroll
        for (int j = 0; j < 4; j++) {
            int n = n0 + tx*4 + j;
            out[(size_t)m * D_ + n] = acc[i][j] + bias[n];
        }
    }
}

extern "C" void kernel_launch(void* const* d_in, const int* in_sizes, int n_in,
                              void* d_out, int out_size)
{
    (void)in_sizes; (void)n_in; (void)out_size;
    const float* query = (const float*)d_in[0];
    const float* key_  = (const float*)d_in[1];
    const float* value = (const float*)d_in[2];
    const float* Wq = (const float*)d_in[3];
    const float* bq = (const float*)d_in[4];
    const float* Wk = (const float*)d_in[5];
    const float* bk = (const float*)d_in[6];
    const float* Wv = (const float*)d_in[7];
    const float* bv = (const float*)d_in[8];
    const float* Wo = (const float*)d_in[9];
    const float* bo = (const float*)d_in[10];

    float* out  = (float*)d_out;
    float* attn = out + OUT_OFF;

    dim3 tpb(256);
    dim3 grid_proj(D_ / 64, MROWS / 64);          // 16 x 64
    proj_kernel<<<grid_proj, tpb>>>(query, Wq, bq, 0);
    proj_kernel<<<grid_proj, tpb>>>(key_,  Wk, bk, 1);
    proj_kernel<<<grid_proj, tpb>>>(value, Wv, bv, 2);

    dim3 grid_sc(S_ / 64, S_ / 64, BH_);          // 32 x 32 x 32
    scores_kernel<<<grid_sc, tpb>>>(attn);

    softmax_kernel<<<BH_ * S_, tpb>>>(attn);      // 65536 blocks

    dim3 grid_av(1, S_ / 64, BH_);                // 1 x 32 x 32
    av_kernel<<<grid_av, tpb>>>(attn);

    dim3 grid_out(D_ / 64, MROWS / 64);           // 16 x 64
    out_kernel<<<grid_out, tpb>>>(Wo, bo, out);
}